// round 4
// baseline (speedup 1.0000x reference)
#include <cuda_runtime.h>
#include <cuda_bf16.h>

#define B_DIM 8
#define N_PTS 2048
#define NPTS_TOTAL (B_DIM * N_PTS)
#define C_OUT 128
#define H_DIM 64
#define NSAMPLE 64
#define R2 0.36f

// Scratch (allocation-free rule: __device__ globals)
__device__ float  g_f[NPTS_TOTAL * C_OUT];     // per-point 128-dim features (8 MB)
__device__ float4 g_xpad[NPTS_TOTAL];          // (x, y, z, x^2+y^2+z^2)
__device__ int    g_idx[NPTS_TOTAL * NSAMPLE]; // padded neighbor lists (4 MB)

// ---------------------------------------------------------------------------
// Kernel 1: per-point MLP features. Warp processes 4 points at a time
// (8 per warp total). W2 staged as [k][128ch] (stride 132 floats) so the
// k-loop does ONE LDS.128 per k, reused across 4 points -> 16 FFMA / iter.
// ---------------------------------------------------------------------------
#define W2_STRIDE 132   // floats per k-row; mult of 4 (aligned f4), 4-way STS conflict only

__global__ __launch_bounds__(256)
void feat_kernel(const float* __restrict__ x,
                 const float* __restrict__ W1,
                 const float* __restrict__ b1,
                 const float* __restrict__ W2,
                 const float* __restrict__ b2)
{
    __shared__ float sW1[H_DIM * 3];
    __shared__ float sb1[H_DIM];
    __shared__ float sW2[H_DIM * W2_STRIDE];   // [k][c]
    __shared__ float sb2[C_OUT];
    __shared__ float sh1[8][4][H_DIM];         // [warp][pt][k]

    const int tid = threadIdx.x;
    for (int i = tid; i < H_DIM * 3; i += 256) sW1[i] = W1[i];
    for (int i = tid; i < H_DIM;     i += 256) sb1[i] = b1[i];
    for (int i = tid; i < C_OUT;     i += 256) sb2[i] = b2[i];
    // W2 row-major [o][k]: coalesced read (index i == o*64+k), transposed STS
    for (int i = tid; i < C_OUT * H_DIM; i += 256) {
        const int o = i >> 6, k = i & 63;
        sW2[k * W2_STRIDE + o] = W2[i];
    }
    __syncthreads();

    const int warp = tid >> 5;
    const int lane = tid & 31;
    const int pt   = lane >> 3;         // 0..3: which point this lane helps in h1
    const int sub  = lane & 7;

    const float4 bz = *reinterpret_cast<const float4*>(&sb2[lane * 4]);

    // warp handles 8 points: 2 groups of 4
    const int warp_base = (blockIdx.x * 8 + warp) * 8;

    #pragma unroll
    for (int grp = 0; grp < 2; grp++) {
        const int p0 = warp_base + grp * 4;
        const int p  = p0 + pt;

        // coords of this lane's point (L1-broadcast LDGs)
        const float x0 = x[p * 3 + 0];
        const float x1 = x[p * 3 + 1];
        const float x2 = x[p * 3 + 2];
        if (sub == 0) {
            // match reference: sq = sum(x*x) left-to-right
            float s = x0 * x0;
            s = s + x1 * x1;
            s = s + x2 * x2;
            g_xpad[p] = make_float4(x0, x1, x2, s);
        }
        // h1: 8 rows per lane for its point
        #pragma unroll
        for (int s8 = 0; s8 < 8; s8++) {
            const int r = sub + 8 * s8;
            float v = fmaf(sW1[r * 3 + 2], x2,
                      fmaf(sW1[r * 3 + 1], x1, sW1[r * 3 + 0] * x0)) + sb1[r];
            sh1[warp][pt][r] = fmaxf(v, 0.0f);
        }
        __syncwarp();

        float4 a0 = bz, a1 = bz, a2 = bz, a3 = bz;
        const float4* __restrict__ w2row =
            reinterpret_cast<const float4*>(sW2) ;  // indexed per-k below

        #pragma unroll 4
        for (int k = 0; k < H_DIM; k++) {
            const float4 wv =
                *reinterpret_cast<const float4*>(&sW2[k * W2_STRIDE + lane * 4]);
            const float h0 = sh1[warp][0][k];
            const float h1v = sh1[warp][1][k];
            const float h2v = sh1[warp][2][k];
            const float h3v = sh1[warp][3][k];
            a0.x = fmaf(wv.x, h0, a0.x);  a0.y = fmaf(wv.y, h0, a0.y);
            a0.z = fmaf(wv.z, h0, a0.z);  a0.w = fmaf(wv.w, h0, a0.w);
            a1.x = fmaf(wv.x, h1v, a1.x); a1.y = fmaf(wv.y, h1v, a1.y);
            a1.z = fmaf(wv.z, h1v, a1.z); a1.w = fmaf(wv.w, h1v, a1.w);
            a2.x = fmaf(wv.x, h2v, a2.x); a2.y = fmaf(wv.y, h2v, a2.y);
            a2.z = fmaf(wv.z, h2v, a2.z); a2.w = fmaf(wv.w, h2v, a2.w);
            a3.x = fmaf(wv.x, h3v, a3.x); a3.y = fmaf(wv.y, h3v, a3.y);
            a3.z = fmaf(wv.z, h3v, a3.z); a3.w = fmaf(wv.w, h3v, a3.w);
        }
        (void)w2row;

        float4 r0, r1, r2, r3;
        r0.x = fmaxf(a0.x, 0.f); r0.y = fmaxf(a0.y, 0.f); r0.z = fmaxf(a0.z, 0.f); r0.w = fmaxf(a0.w, 0.f);
        r1.x = fmaxf(a1.x, 0.f); r1.y = fmaxf(a1.y, 0.f); r1.z = fmaxf(a1.z, 0.f); r1.w = fmaxf(a1.w, 0.f);
        r2.x = fmaxf(a2.x, 0.f); r2.y = fmaxf(a2.y, 0.f); r2.z = fmaxf(a2.z, 0.f); r2.w = fmaxf(a2.w, 0.f);
        r3.x = fmaxf(a3.x, 0.f); r3.y = fmaxf(a3.y, 0.f); r3.z = fmaxf(a3.z, 0.f); r3.w = fmaxf(a3.w, 0.f);
        *reinterpret_cast<float4*>(&g_f[(size_t)(p0 + 0) * C_OUT + lane * 4]) = r0;
        *reinterpret_cast<float4*>(&g_f[(size_t)(p0 + 1) * C_OUT + lane * 4]) = r1;
        *reinterpret_cast<float4*>(&g_f[(size_t)(p0 + 2) * C_OUT + lane * 4]) = r2;
        *reinterpret_cast<float4*>(&g_f[(size_t)(p0 + 3) * C_OUT + lane * 4]) = r3;
        __syncwarp();
    }
}

// ---------------------------------------------------------------------------
// Kernel 2: neighbor scan. One warp per query; NO block-level sync, warps
// retire independently (no scan-skew tax). Writes index list padded to
// exactly NSAMPLE with duplicates of the last accepted index (duplicates are
// no-ops under max). Every point here has >= NSAMPLE in-radius neighbors,
// but padding also covers the general case.
// ---------------------------------------------------------------------------
__global__ __launch_bounds__(256)
void scan_kernel()
{
    __shared__ int sidx[8][NSAMPLE];

    const int warp = threadIdx.x >> 5;
    const int lane = threadIdx.x & 31;
    const int gwarp = blockIdx.x * 8 + warp;
    const int b = gwarp >> 11;
    const int n = gwarp & (N_PTS - 1);

    const float4* __restrict__ xb = g_xpad + b * N_PTS;
    const float4 qc = xb[n];

    int found = 0;
    for (int pb = 0; pb < N_PTS && found < NSAMPLE; pb += 32) {
        const float4 r = xb[pb + lane];
        const float dot  = fmaf(qc.z, r.z, fmaf(qc.y, r.y, qc.x * r.x));
        const float dist = (qc.w + r.w) - 2.0f * dot;
        const bool  qual = !(dist > R2);
        const unsigned m = __ballot_sync(0xffffffffu, qual);
        const int need = NSAMPLE - found;
        const int rank = __popc(m & ((1u << lane) - 1u));
        const bool take = qual && (rank < need);
        if (take) sidx[warp][found + rank] = pb + lane;
        found += __popc(__ballot_sync(0xffffffffu, take));
    }
    __syncwarp();
    const int last = sidx[warp][found - 1];   // found >= 1 (self qualifies)
    for (int i = found + lane; i < NSAMPLE; i += 32) sidx[warp][i] = last;
    __syncwarp();

    // burst-write 256B per query, int4
    if (lane < NSAMPLE / 4) {
        reinterpret_cast<int4*>(g_idx)[gwarp * (NSAMPLE / 4) + lane] =
            reinterpret_cast<int4*>(sidx[warp])[lane];
    }
}

// ---------------------------------------------------------------------------
// Kernel 3: uniform gather-max. 1024 threads = 32 warps = 32 consecutive
// queries. Exactly NSAMPLE/4 iterations of int4-indexed 4x LDG.128, then
// smem transpose for fully coalesced output stores.
// ---------------------------------------------------------------------------
__global__ __launch_bounds__(1024, 1)
void gather_kernel(float* __restrict__ out)
{
    __shared__ int4  sidx4[32][NSAMPLE / 4];
    __shared__ float sout[C_OUT][33];

    const int tid  = threadIdx.x;
    const int q    = tid >> 5;
    const int lane = tid & 31;

    const int b  = blockIdx.x >> 6;
    const int n0 = (blockIdx.x & 63) << 5;
    const int gq = (b << 11) + n0 + q;

    if (lane < NSAMPLE / 4) {
        sidx4[q][lane] = reinterpret_cast<const int4*>(g_idx)[gq * (NSAMPLE / 4) + lane];
    }
    __syncwarp();

    const float* __restrict__ fb = g_f + (size_t)b * N_PTS * C_OUT;
    const int coff = lane * 4;

    float4 a0 = make_float4(0.f, 0.f, 0.f, 0.f);
    float4 a1 = a0, a2 = a0, a3 = a0;        // relu outputs >= 0

    #pragma unroll
    for (int j = 0; j < NSAMPLE / 4; j++) {
        const int4 iv = sidx4[q][j];
        const float4 v0 = *reinterpret_cast<const float4*>(fb + (size_t)iv.x * C_OUT + coff);
        const float4 v1 = *reinterpret_cast<const float4*>(fb + (size_t)iv.y * C_OUT + coff);
        const float4 v2 = *reinterpret_cast<const float4*>(fb + (size_t)iv.z * C_OUT + coff);
        const float4 v3 = *reinterpret_cast<const float4*>(fb + (size_t)iv.w * C_OUT + coff);
        a0.x = fmaxf(a0.x, v0.x); a0.y = fmaxf(a0.y, v0.y);
        a0.z = fmaxf(a0.z, v0.z); a0.w = fmaxf(a0.w, v0.w);
        a1.x = fmaxf(a1.x, v1.x); a1.y = fmaxf(a1.y, v1.y);
        a1.z = fmaxf(a1.z, v1.z); a1.w = fmaxf(a1.w, v1.w);
        a2.x = fmaxf(a2.x, v2.x); a2.y = fmaxf(a2.y, v2.y);
        a2.z = fmaxf(a2.z, v2.z); a2.w = fmaxf(a2.w, v2.w);
        a3.x = fmaxf(a3.x, v3.x); a3.y = fmaxf(a3.y, v3.y);
        a3.z = fmaxf(a3.z, v3.z); a3.w = fmaxf(a3.w, v3.w);
    }
    a0.x = fmaxf(fmaxf(a0.x, a1.x), fmaxf(a2.x, a3.x));
    a0.y = fmaxf(fmaxf(a0.y, a1.y), fmaxf(a2.y, a3.y));
    a0.z = fmaxf(fmaxf(a0.z, a1.z), fmaxf(a2.z, a3.z));
    a0.w = fmaxf(fmaxf(a0.w, a1.w), fmaxf(a2.w, a3.w));

    sout[coff + 0][q] = a0.x;
    sout[coff + 1][q] = a0.y;
    sout[coff + 2][q] = a0.z;
    sout[coff + 3][q] = a0.w;
    __syncthreads();

    // out shape (B, 128, N); consecutive lanes -> consecutive n (128B runs)
    const int nq = tid & 31;
    const int c0 = tid >> 5;
    float* ob = out + ((size_t)b * C_OUT) * N_PTS + n0 + nq;
    #pragma unroll
    for (int i = 0; i < 4; i++) {
        const int c = c0 + 32 * i;
        ob[(size_t)c * N_PTS] = sout[c][nq];
    }
}

extern "C" void kernel_launch(void* const* d_in, const int* in_sizes, int n_in,
                              void* d_out, int out_size)
{
    const float* x  = (const float*)d_in[0];
    const float* W1 = (const float*)d_in[1];
    const float* b1 = (const float*)d_in[2];
    const float* W2 = (const float*)d_in[3];
    const float* b2 = (const float*)d_in[4];
    float* out = (float*)d_out;

    feat_kernel<<<NPTS_TOTAL / 64, 256>>>(x, W1, b1, W2, b2);  // 256 blocks
    scan_kernel<<<NPTS_TOTAL / 8, 256>>>();                    // 2048 blocks
    gather_kernel<<<NPTS_TOTAL / 32, 1024>>>(out);             // 512 blocks
}

// round 7
// speedup vs baseline: 1.2536x; 1.2536x over previous
#include <cuda_runtime.h>
#include <cuda_bf16.h>

#define B_DIM 8
#define N_PTS 2048
#define NPTS_TOTAL (B_DIM * N_PTS)
#define C_OUT 128
#define H_DIM 64
#define NSAMPLE 64
#define R2 0.36f

// Scratch (allocation-free rule: __device__ globals)
__device__ float  g_f[NPTS_TOTAL * C_OUT];   // per-point 128-dim features (8 MB)
__device__ float4 g_xpad[NPTS_TOTAL];        // (x, y, z, x^2+y^2+z^2)

// ---------------------------------------------------------------------------
// Kernel 1: per-point MLP features.
// 4 threads per point (lane = pt*4 + q, pt in [0,8), q in [0,4)); each thread
// computes channels c = q*32 .. q*32+31. 65536 threads total -> ~14 warps/SM.
// h1 per point in smem (stride 68 -> pt gives distinct bank groups).
// W2 in smem with skew c*68 + (c>>5)*8:
//   - staging STS (fixed c, consecutive k) -> consecutive banks, conflict-free
//   - inner LDS.128 (fixed i,j; q varies)  -> 4 distinct addrs at bank offsets
//     {4*ro + 8q}, conflict-free, 1 wavefront per LDS.
// Inner loop: 512 LDS.128 + 2048 FFMA per warp -> FFMA-issue-bound.
// ---------------------------------------------------------------------------
#define SW2_IDX(c, k) ((c) * 68 + ((c) >> 5) * 8 + (k))
#define SW2_SIZE (SW2_IDX(127, 63) + 1)
#define SH1_WSTRIDE (8 * 68)   // 8 points * 68 floats

__global__ __launch_bounds__(128)
void feat_kernel(const float* __restrict__ x,
                 const float* __restrict__ W1,
                 const float* __restrict__ b1,
                 const float* __restrict__ W2,
                 const float* __restrict__ b2)
{
    __shared__ float sW2[SW2_SIZE];            // ~34.9 KB
    __shared__ float sh1[4 * SH1_WSTRIDE];     // 8.7 KB
    __shared__ float sW1[H_DIM * 3];
    __shared__ float sb1[H_DIM];
    __shared__ float sb2[C_OUT];

    const int tid = threadIdx.x;
    for (int idx = tid; idx < C_OUT * H_DIM; idx += 128) {
        const int c = idx >> 6, k = idx & 63;
        sW2[SW2_IDX(c, k)] = W2[idx];          // coalesced LDG, conflict-free STS
    }
    for (int i = tid; i < H_DIM * 3; i += 128) sW1[i] = W1[i];
    for (int i = tid; i < H_DIM;     i += 128) sb1[i] = b1[i];
    for (int i = tid; i < C_OUT;     i += 128) sb2[i] = b2[i];
    __syncthreads();

    const int warp = tid >> 5;
    const int lane = tid & 31;
    const int pt   = lane >> 2;                // point within warp, 0..7
    const int q    = lane & 3;                 // channel group, 0..3

    const int p = blockIdx.x * 32 + warp * 8 + pt;

    // coords (4 threads of a point share addresses -> L1 broadcast)
    const float x0 = x[p * 3 + 0];
    const float x1 = x[p * 3 + 1];
    const float x2 = x[p * 3 + 2];
    if (q == 0) {
        // match reference: sq = sum(x*x) left-to-right
        float s = x0 * x0;
        s = s + x1 * x1;
        s = s + x2 * x2;
        g_xpad[p] = make_float4(x0, x1, x2, s);
    }

    // h1: this thread computes rows q*16 .. q*16+15 of its point
    float* h1p = &sh1[warp * SH1_WSTRIDE + pt * 68];
    #pragma unroll
    for (int t = 0; t < 16; t++) {
        const int r = q * 16 + t;
        float v = fmaf(sW1[r * 3 + 2], x2,
                  fmaf(sW1[r * 3 + 1], x1, sW1[r * 3 + 0] * x0)) + sb1[r];
        h1p[r] = fmaxf(v, 0.0f);
    }
    __syncwarp();

    // accumulators: 8 float4 = 32 channels (c = q*32 + i*4 + j)
    float4 acc[8];
    #pragma unroll
    for (int i = 0; i < 8; i++)
        acc[i] = *reinterpret_cast<const float4*>(&sb2[q * 32 + i * 4]);

    #pragma unroll 4
    for (int k4 = 0; k4 < 16; k4++) {
        const float4 h = *reinterpret_cast<const float4*>(&h1p[k4 * 4]);
        #pragma unroll
        for (int i = 0; i < 8; i++) {
            const int cbase = q * 32 + i * 4;
            #pragma unroll
            for (int j = 0; j < 4; j++) {
                const float4 w =
                    *reinterpret_cast<const float4*>(&sW2[SW2_IDX(cbase + j, k4 * 4)]);
                float a = (&acc[i].x)[j];
                a = fmaf(w.x, h.x, a);
                a = fmaf(w.y, h.y, a);
                a = fmaf(w.z, h.z, a);
                a = fmaf(w.w, h.w, a);
                (&acc[i].x)[j] = a;
            }
        }
    }

    float* fp = &g_f[(size_t)p * C_OUT + q * 32];
    #pragma unroll
    for (int i = 0; i < 8; i++) {
        float4 r;
        r.x = fmaxf(acc[i].x, 0.0f);
        r.y = fmaxf(acc[i].y, 0.0f);
        r.z = fmaxf(acc[i].z, 0.0f);
        r.w = fmaxf(acc[i].w, 0.0f);
        *reinterpret_cast<float4*>(fp + i * 4) = r;
    }
}

// ---------------------------------------------------------------------------
// Kernel 2 (fused): 512 threads = 16 warps = 16 consecutive queries.
// Phase 1: per-warp ballot scan of first NSAMPLE qualifying indices -> smem,
//          padded to exactly NSAMPLE with the last accepted index
//          (duplicates are no-ops under max).
// Phase 2: fixed 16-iteration gather, 4 independent LDG.128 chains.
// Phase 3: smem transpose -> 64B-coalesced output stores.
// ---------------------------------------------------------------------------
__global__ __launch_bounds__(512, 2)
void group_max_kernel(float* __restrict__ out)
{
    __shared__ int   sidx[16][NSAMPLE];
    __shared__ float sout[C_OUT][17];

    const int tid  = threadIdx.x;
    const int q    = tid >> 5;               // local query 0..15
    const int lane = tid & 31;

    const int b  = blockIdx.x >> 7;          // 128 blocks per batch
    const int n0 = (blockIdx.x & 127) << 4;
    const int n  = n0 + q;

    const float4* __restrict__ xb = g_xpad + b * N_PTS;
    const float*  __restrict__ fb = g_f + (size_t)b * N_PTS * C_OUT;

    const float4 qc = xb[n];

    // ---- Phase 1: scan ----
    int found = 0;
    for (int pb = 0; pb < N_PTS && found < NSAMPLE; pb += 32) {
        const float4 r = xb[pb + lane];
        const float dot  = fmaf(qc.z, r.z, fmaf(qc.y, r.y, qc.x * r.x));
        const float dist = (qc.w + r.w) - 2.0f * dot;
        const bool  qual = !(dist > R2);
        const unsigned m = __ballot_sync(0xffffffffu, qual);
        const int need = NSAMPLE - found;
        const int rank = __popc(m & ((1u << lane) - 1u));
        const bool take = qual && (rank < need);
        if (take) sidx[q][found + rank] = pb + lane;
        found += __popc(__ballot_sync(0xffffffffu, take));
    }
    __syncwarp();
    const int lastv = sidx[q][found - 1];    // found >= 1 (self qualifies)
    for (int i = found + lane; i < NSAMPLE; i += 32) sidx[q][i] = lastv;
    __syncwarp();

    // ---- Phase 2: uniform gather-max, 4-wide ILP ----
    const int4* __restrict__ sidx4 = reinterpret_cast<const int4*>(sidx[q]);
    const int coff = lane * 4;

    float4 a0 = make_float4(0.f, 0.f, 0.f, 0.f);
    float4 a1 = a0, a2 = a0, a3 = a0;        // relu outputs >= 0

    #pragma unroll 4
    for (int j = 0; j < NSAMPLE / 4; j++) {
        const int4 iv = sidx4[j];
        const float4 v0 = *reinterpret_cast<const float4*>(fb + (size_t)iv.x * C_OUT + coff);
        const float4 v1 = *reinterpret_cast<const float4*>(fb + (size_t)iv.y * C_OUT + coff);
        const float4 v2 = *reinterpret_cast<const float4*>(fb + (size_t)iv.z * C_OUT + coff);
        const float4 v3 = *reinterpret_cast<const float4*>(fb + (size_t)iv.w * C_OUT + coff);
        a0.x = fmaxf(a0.x, v0.x); a0.y = fmaxf(a0.y, v0.y);
        a0.z = fmaxf(a0.z, v0.z); a0.w = fmaxf(a0.w, v0.w);
        a1.x = fmaxf(a1.x, v1.x); a1.y = fmaxf(a1.y, v1.y);
        a1.z = fmaxf(a1.z, v1.z); a1.w = fmaxf(a1.w, v1.w);
        a2.x = fmaxf(a2.x, v2.x); a2.y = fmaxf(a2.y, v2.y);
        a2.z = fmaxf(a2.z, v2.z); a2.w = fmaxf(a2.w, v2.w);
        a3.x = fmaxf(a3.x, v3.x); a3.y = fmaxf(a3.y, v3.y);
        a3.z = fmaxf(a3.z, v3.z); a3.w = fmaxf(a3.w, v3.w);
    }
    a0.x = fmaxf(fmaxf(a0.x, a1.x), fmaxf(a2.x, a3.x));
    a0.y = fmaxf(fmaxf(a0.y, a1.y), fmaxf(a2.y, a3.y));
    a0.z = fmaxf(fmaxf(a0.z, a1.z), fmaxf(a2.z, a3.z));
    a0.w = fmaxf(fmaxf(a0.w, a1.w), fmaxf(a2.w, a3.w));

    // ---- Phase 3: transpose + coalesced store ----
    sout[coff + 0][q] = a0.x;
    sout[coff + 1][q] = a0.y;
    sout[coff + 2][q] = a0.z;
    sout[coff + 3][q] = a0.w;
    __syncthreads();

    // out shape (B, 128, N); consecutive tid -> consecutive n (64B runs)
    const int nq = tid & 15;
    const int c0 = tid >> 4;                 // 0..31
    float* ob = out + ((size_t)b * C_OUT) * N_PTS + n0 + nq;
    #pragma unroll
    for (int i = 0; i < 4; i++) {
        const int c = c0 + 32 * i;
        ob[(size_t)c * N_PTS] = sout[c][nq];
    }
}

extern "C" void kernel_launch(void* const* d_in, const int* in_sizes, int n_in,
                              void* d_out, int out_size)
{
    const float* x  = (const float*)d_in[0];
    const float* W1 = (const float*)d_in[1];
    const float* b1 = (const float*)d_in[2];
    const float* W2 = (const float*)d_in[3];
    const float* b2 = (const float*)d_in[4];
    float* out = (float*)d_out;

    feat_kernel<<<NPTS_TOTAL / 32, 128>>>(x, W1, b1, W2, b2);   // 512 blocks
    group_max_kernel<<<NPTS_TOTAL / 16, 512>>>(out);            // 1024 blocks
}

// round 8
// speedup vs baseline: 1.7963x; 1.4329x over previous
#include <cuda_runtime.h>
#include <cuda_bf16.h>
#include <cuda_fp16.h>

#define B_DIM 8
#define N_PTS 2048
#define NPTS_TOTAL (B_DIM * N_PTS)
#define C_OUT 128
#define H_DIM 64
#define NSAMPLE 64
#define R2 0.36f

// Scratch (allocation-free rule: __device__ globals)
__device__ __half g_fh[NPTS_TOTAL * C_OUT];  // per-point features, fp16 (4 MB)
__device__ float4 g_xpad[NPTS_TOTAL];        // (x, y, z, x^2+y^2+z^2)

// ---------------------------------------------------------------------------
// Kernel 1: per-point MLP features.  POINT = LANE layout:
//   block = 128 threads = 4 warps; block covers 32 points (p = blk*32 + lane).
//   Warp w owns channels w*32 .. w*32+31 of all 32 points.
//   => every W2 smem read is warp-UNIFORM (broadcast, conflict-free, ~free);
//      total W2 LDS traffic ~16MB chip-wide (was ~512MB). FFMA-bound (~8us).
// h1 staged in smem: thread (w, lane) computes rows w*16..w*16+15 of point
// `lane`, then each thread reads its own point's h1 as float4s.
// Output fp16 (half2 pairs), 32 channels per thread.
// ---------------------------------------------------------------------------
#define SH1_STRIDE 68

__global__ __launch_bounds__(128)
void feat_kernel(const float* __restrict__ x,
                 const float* __restrict__ W1,
                 const float* __restrict__ b1,
                 const float* __restrict__ W2,
                 const float* __restrict__ b2)
{
    __shared__ float sW2t[C_OUT][68];          // [c][k], 34.8 KB
    __shared__ float sh1[32 * SH1_STRIDE];     // [point][row], 8.7 KB
    __shared__ float sW1[H_DIM * 3];
    __shared__ float sb1[H_DIM];
    __shared__ float sb2[C_OUT];

    const int tid = threadIdx.x;
    // W2 row-major [c][k] (c*64+k): coalesced LDG, conflict-free STS
    for (int idx = tid; idx < C_OUT * H_DIM; idx += 128) {
        const int c = idx >> 6, k = idx & 63;
        sW2t[c][k] = W2[idx];
    }
    for (int i = tid; i < H_DIM * 3; i += 128) sW1[i] = W1[i];
    for (int i = tid; i < H_DIM;     i += 128) sb1[i] = b1[i];
    for (int i = tid; i < C_OUT;     i += 128) sb2[i] = b2[i];
    __syncthreads();

    const int warpId = tid >> 5;               // 0..3 = channel quarter
    const int lane   = tid & 31;
    const int p      = blockIdx.x * 32 + lane; // this thread's point

    const float x0 = x[p * 3 + 0];
    const float x1 = x[p * 3 + 1];
    const float x2 = x[p * 3 + 2];
    if (warpId == 0) {
        // match reference: sq = sum(x*x) left-to-right
        float s = x0 * x0;
        s = s + x1 * x1;
        s = s + x2 * x2;
        g_xpad[p] = make_float4(x0, x1, x2, s);
    }

    // h1 rows warpId*16 .. +15 for point `lane` (sW1/sb1 reads are uniform)
    #pragma unroll
    for (int t = 0; t < 16; t++) {
        const int r = warpId * 16 + t;
        float v = fmaf(sW1[r * 3 + 2], x2,
                  fmaf(sW1[r * 3 + 1], x1, sW1[r * 3 + 0] * x0)) + sb1[r];
        sh1[lane * SH1_STRIDE + r] = fmaxf(v, 0.0f);
    }
    __syncthreads();

    // 32 channels per thread: c = warpId*32 + i*4 + jj
    float4 acc[8];
    #pragma unroll
    for (int i = 0; i < 8; i++)
        acc[i] = *reinterpret_cast<const float4*>(&sb2[warpId * 32 + i * 4]);

    const float* h1p = &sh1[lane * SH1_STRIDE];
    #pragma unroll 4
    for (int k4 = 0; k4 < 16; k4++) {
        const float4 h = *reinterpret_cast<const float4*>(&h1p[k4 * 4]);
        #pragma unroll
        for (int i = 0; i < 8; i++) {
            #pragma unroll
            for (int jj = 0; jj < 4; jj++) {
                // warp-uniform address -> LDS broadcast
                const float4 w = *reinterpret_cast<const float4*>(
                    &sW2t[warpId * 32 + i * 4 + jj][k4 * 4]);
                float a = (&acc[i].x)[jj];
                a = fmaf(w.x, h.x, a);
                a = fmaf(w.y, h.y, a);
                a = fmaf(w.z, h.z, a);
                a = fmaf(w.w, h.w, a);
                (&acc[i].x)[jj] = a;
            }
        }
    }

    // relu -> fp16, store 32 channels (4x STG.64-equivalent via uint2)
    __half* fp = &g_fh[(size_t)p * C_OUT + warpId * 32];
    #pragma unroll
    for (int i = 0; i < 8; i++) {
        const float rx = fmaxf(acc[i].x, 0.0f);
        const float ry = fmaxf(acc[i].y, 0.0f);
        const float rz = fmaxf(acc[i].z, 0.0f);
        const float rw = fmaxf(acc[i].w, 0.0f);
        __half2 lo = __floats2half2_rn(rx, ry);   // .x = channel c (low half)
        __half2 hi = __floats2half2_rn(rz, rw);
        uint2 v;
        v.x = *reinterpret_cast<unsigned*>(&lo);
        v.y = *reinterpret_cast<unsigned*>(&hi);
        *reinterpret_cast<uint2*>(fp + i * 4) = v;
    }
}

// ---------------------------------------------------------------------------
// Kernel 2 (fused): 512 threads = 16 warps = 16 consecutive queries.
// Phase 1: per-warp ballot scan -> first NSAMPLE qualifying indices in smem,
//          padded to exactly NSAMPLE with the last accepted index
//          (duplicates are no-ops under max). fp32, bit-identical to before.
// Phase 2: fixed 8-iteration gather, 8 independent LDG.64 chains (fp16 rows,
//          256B/neighbor = 2 L1 wavefronts), HMNMX2 accumulate.
// Phase 3: fp32 convert + smem transpose -> coalesced output stores.
// ---------------------------------------------------------------------------
__global__ __launch_bounds__(512, 2)
void group_max_kernel(float* __restrict__ out)
{
    __shared__ int   sidx[16][NSAMPLE];
    __shared__ float sout[C_OUT][17];

    const int tid  = threadIdx.x;
    const int q    = tid >> 5;               // local query 0..15
    const int lane = tid & 31;

    const int b  = blockIdx.x >> 7;          // 128 blocks per batch
    const int n0 = (blockIdx.x & 127) << 4;
    const int n  = n0 + q;

    const float4* __restrict__ xb = g_xpad + b * N_PTS;
    const __half* __restrict__ fbh = g_fh + (size_t)b * N_PTS * C_OUT;

    const float4 qc = xb[n];

    // ---- Phase 1: scan (unchanged semantics) ----
    int found = 0;
    for (int pb = 0; pb < N_PTS && found < NSAMPLE; pb += 32) {
        const float4 r = xb[pb + lane];
        const float dot  = fmaf(qc.z, r.z, fmaf(qc.y, r.y, qc.x * r.x));
        const float dist = (qc.w + r.w) - 2.0f * dot;
        const bool  qual = !(dist > R2);
        const unsigned m = __ballot_sync(0xffffffffu, qual);
        const int need = NSAMPLE - found;
        const int rank = __popc(m & ((1u << lane) - 1u));
        const bool take = qual && (rank < need);
        if (take) sidx[q][found + rank] = pb + lane;
        found += __popc(__ballot_sync(0xffffffffu, take));
    }
    __syncwarp();
    const int lastv = sidx[q][found - 1];    // found >= 1 (self qualifies)
    for (int i = found + lane; i < NSAMPLE; i += 32) sidx[q][i] = lastv;
    __syncwarp();

    // ---- Phase 2: uniform gather-max, 8-wide ILP, fp16 ----
    const int4* __restrict__ sidx4 = reinterpret_cast<const int4*>(sidx[q]);
    const int hoff = lane * 4;               // channel offset in halves

    const __half2 z2 = __float2half2_rn(0.0f);   // relu outputs >= 0
    __half2 aA[8], aB[8];
    #pragma unroll
    for (int i = 0; i < 8; i++) { aA[i] = z2; aB[i] = z2; }

    #pragma unroll 2
    for (int j = 0; j < NSAMPLE / 8; j++) {
        const int4 iv0 = sidx4[2 * j + 0];
        const int4 iv1 = sidx4[2 * j + 1];
        uint2 v[8];
        v[0] = *reinterpret_cast<const uint2*>(fbh + (size_t)iv0.x * C_OUT + hoff);
        v[1] = *reinterpret_cast<const uint2*>(fbh + (size_t)iv0.y * C_OUT + hoff);
        v[2] = *reinterpret_cast<const uint2*>(fbh + (size_t)iv0.z * C_OUT + hoff);
        v[3] = *reinterpret_cast<const uint2*>(fbh + (size_t)iv0.w * C_OUT + hoff);
        v[4] = *reinterpret_cast<const uint2*>(fbh + (size_t)iv1.x * C_OUT + hoff);
        v[5] = *reinterpret_cast<const uint2*>(fbh + (size_t)iv1.y * C_OUT + hoff);
        v[6] = *reinterpret_cast<const uint2*>(fbh + (size_t)iv1.z * C_OUT + hoff);
        v[7] = *reinterpret_cast<const uint2*>(fbh + (size_t)iv1.w * C_OUT + hoff);
        #pragma unroll
        for (int i = 0; i < 8; i++) {
            aA[i] = __hmax2(aA[i], *reinterpret_cast<__half2*>(&v[i].x));
            aB[i] = __hmax2(aB[i], *reinterpret_cast<__half2*>(&v[i].y));
        }
    }
    __half2 mA = aA[0], mB = aB[0];
    #pragma unroll
    for (int i = 1; i < 8; i++) {
        mA = __hmax2(mA, aA[i]);
        mB = __hmax2(mB, aB[i]);
    }
    const float2 fA = __half22float2(mA);    // channels 4l, 4l+1
    const float2 fB = __half22float2(mB);    // channels 4l+2, 4l+3

    // ---- Phase 3: transpose + coalesced store ----
    sout[hoff + 0][q] = fA.x;
    sout[hoff + 1][q] = fA.y;
    sout[hoff + 2][q] = fB.x;
    sout[hoff + 3][q] = fB.y;
    __syncthreads();

    // out shape (B, 128, N); consecutive tid -> consecutive n (64B runs)
    const int nq = tid & 15;
    const int c0 = tid >> 4;                 // 0..31
    float* ob = out + ((size_t)b * C_OUT) * N_PTS + n0 + nq;
    #pragma unroll
    for (int i = 0; i < 4; i++) {
        const int c = c0 + 32 * i;
        ob[(size_t)c * N_PTS] = sout[c][nq];
    }
}

extern "C" void kernel_launch(void* const* d_in, const int* in_sizes, int n_in,
                              void* d_out, int out_size)
{
    const float* x  = (const float*)d_in[0];
    const float* W1 = (const float*)d_in[1];
    const float* b1 = (const float*)d_in[2];
    const float* W2 = (const float*)d_in[3];
    const float* b2 = (const float*)d_in[4];
    float* out = (float*)d_out;

    feat_kernel<<<NPTS_TOTAL / 32, 128>>>(x, W1, b1, W2, b2);   // 512 blocks
    group_max_kernel<<<NPTS_TOTAL / 16, 512>>>(out);            // 1024 blocks
}

// round 9
// speedup vs baseline: 1.8173x; 1.0117x over previous
#include <cuda_runtime.h>
#include <cuda_bf16.h>
#include <cuda_fp16.h>

#define B_DIM 8
#define N_PTS 2048
#define NPTS_TOTAL (B_DIM * N_PTS)
#define C_OUT 128
#define H_DIM 64
#define NSAMPLE 64
#define R2 0.36f

// Scratch (allocation-free rule: __device__ globals)
__device__ __half g_fh[NPTS_TOTAL * C_OUT];  // per-point features, fp16 (4 MB)
__device__ float4 g_xpad[NPTS_TOTAL];        // (x, y, z, x^2+y^2+z^2)

// ---- packed fp32x2 helpers (sm_100+ FFMA2; numerically identical to FFMA) --
__device__ __forceinline__ unsigned long long ffma2(unsigned long long a,
                                                    unsigned long long b,
                                                    unsigned long long c)
{
    unsigned long long d;
    asm("fma.rn.f32x2 %0, %1, %2, %3;" : "=l"(d) : "l"(a), "l"(b), "l"(c));
    return d;
}
__device__ __forceinline__ unsigned long long bcast2(float h)
{
    unsigned long long d;
    const unsigned hb = __float_as_uint(h);
    asm("mov.b64 %0, {%1, %1};" : "=l"(d) : "r"(hb));
    return d;
}

// ---------------------------------------------------------------------------
// Kernel 1: per-point MLP features. POINT = LANE layout (warp-uniform W2
// broadcasts), inner product via packed FFMA2: 1024 FFMA2/thread instead of
// 2048 FFMA -> halves fma-pipe time.
// sW2f layout [k][c] (stride 132 floats: 16B-aligned rows, ulonglong2 loads).
// ---------------------------------------------------------------------------
#define SH1_STRIDE 68
#define SW2F_STRIDE 132

__global__ __launch_bounds__(128)
void feat_kernel(const float* __restrict__ x,
                 const float* __restrict__ W1,
                 const float* __restrict__ b1,
                 const float* __restrict__ W2,
                 const float* __restrict__ b2)
{
    __shared__ float sW2f[H_DIM * SW2F_STRIDE];   // [k][c], 33.8 KB
    __shared__ float sh1[32 * SH1_STRIDE];        // [point][row], 8.7 KB
    __shared__ float sW1[H_DIM * 3];
    __shared__ float sb1[H_DIM];
    __shared__ float sb2[C_OUT];

    const int tid = threadIdx.x;
    // W2 row-major [c][k]: coalesced LDG; transposed STS into [k][c]
    for (int idx = tid; idx < C_OUT * H_DIM; idx += 128) {
        const int c = idx >> 6, k = idx & 63;
        sW2f[k * SW2F_STRIDE + c] = W2[idx];
    }
    for (int i = tid; i < H_DIM * 3; i += 128) sW1[i] = W1[i];
    for (int i = tid; i < H_DIM;     i += 128) sb1[i] = b1[i];
    for (int i = tid; i < C_OUT;     i += 128) sb2[i] = b2[i];
    __syncthreads();

    const int warpId = tid >> 5;               // channel quarter 0..3
    const int lane   = tid & 31;
    const int p      = blockIdx.x * 32 + lane; // this thread's point

    const float x0 = x[p * 3 + 0];
    const float x1 = x[p * 3 + 1];
    const float x2 = x[p * 3 + 2];
    if (warpId == 0) {
        // match reference: sq = sum(x*x) left-to-right
        float s = x0 * x0;
        s = s + x1 * x1;
        s = s + x2 * x2;
        g_xpad[p] = make_float4(x0, x1, x2, s);
    }

    // h1 rows warpId*16 .. +15 for point `lane`
    #pragma unroll
    for (int t = 0; t < 16; t++) {
        const int r = warpId * 16 + t;
        float v = fmaf(sW1[r * 3 + 2], x2,
                  fmaf(sW1[r * 3 + 1], x1, sW1[r * 3 + 0] * x0)) + sb1[r];
        sh1[lane * SH1_STRIDE + r] = fmaxf(v, 0.0f);
    }
    __syncthreads();

    // 16 packed channel-pair accumulators: channels warpId*32 + {2t, 2t+1}
    unsigned long long acc[16];
    #pragma unroll
    for (int t = 0; t < 16; t++)
        acc[t] = *reinterpret_cast<const unsigned long long*>(
                     &sb2[warpId * 32 + 2 * t]);

    const float* h1p = &sh1[lane * SH1_STRIDE];
    #pragma unroll 4
    for (int k4 = 0; k4 < 16; k4++) {
        const float4 h = *reinterpret_cast<const float4*>(&h1p[k4 * 4]);
        #pragma unroll
        for (int kk = 0; kk < 3 + 1; kk++) {
            const int k = k4 * 4 + kk;
            const unsigned long long hh = bcast2((&h.x)[kk]);
            const float* base = &sW2f[k * SW2F_STRIDE + warpId * 32];
            #pragma unroll
            for (int g = 0; g < 8; g++) {
                // warp-uniform LDS.128 broadcast: 2 channel pairs
                const ulonglong2 w =
                    *reinterpret_cast<const ulonglong2*>(base + g * 4);
                acc[2 * g + 0] = ffma2(w.x, hh, acc[2 * g + 0]);
                acc[2 * g + 1] = ffma2(w.y, hh, acc[2 * g + 1]);
            }
        }
    }

    // unpack -> relu -> fp16 store (channel pairs are consecutive)
    __half* fp = &g_fh[(size_t)p * C_OUT + warpId * 32];
    #pragma unroll
    for (int t = 0; t < 8; t++) {
        unsigned l0, h0, l1, h1v;
        asm("mov.b64 {%0, %1}, %2;" : "=r"(l0), "=r"(h0) : "l"(acc[2 * t + 0]));
        asm("mov.b64 {%0, %1}, %2;" : "=r"(l1), "=r"(h1v) : "l"(acc[2 * t + 1]));
        const float f0 = fmaxf(__uint_as_float(l0), 0.0f);
        const float f1 = fmaxf(__uint_as_float(h0), 0.0f);
        const float f2 = fmaxf(__uint_as_float(l1), 0.0f);
        const float f3 = fmaxf(__uint_as_float(h1v), 0.0f);
        __half2 lo = __floats2half2_rn(f0, f1);
        __half2 hi = __floats2half2_rn(f2, f3);
        uint2 v;
        v.x = *reinterpret_cast<unsigned*>(&lo);
        v.y = *reinterpret_cast<unsigned*>(&hi);
        *reinterpret_cast<uint2*>(fp + t * 4) = v;
    }
}

// ---------------------------------------------------------------------------
// Kernel 2 (fused): 512 threads = 16 warps = 16 consecutive queries.
// Phase 0: stage batch coords (32KB) into smem -> scan runs off the smem
//          crossbar instead of L1.
// Phase 1: per-warp ballot scan -> first NSAMPLE qualifying indices (fp32,
//          bit-identical classification), padded to NSAMPLE with last index.
// Phase 2: two-rows-per-LDG.128 gather: half-warp covers one 256B feature
//          row, warp loads 2 neighbors per LDG.128; 4 independent chains;
//          cross-half combine with one shfl.xor(16) round.
// Phase 3: fp32 convert + smem transpose -> coalesced output stores.
// ---------------------------------------------------------------------------
__global__ __launch_bounds__(512, 2)
void group_max_kernel(float* __restrict__ out)
{
    __shared__ float4 sxb[N_PTS];            // 32 KB
    __shared__ int    sidx[16][NSAMPLE];     // 4 KB
    __shared__ float  sout[C_OUT][17];       // 8.7 KB

    const int tid  = threadIdx.x;
    const int q    = tid >> 5;               // local query 0..15
    const int lane = tid & 31;

    const int b  = blockIdx.x >> 7;          // 128 blocks per batch
    const int n0 = (blockIdx.x & 127) << 4;
    const int n  = n0 + q;

    // ---- Phase 0: stage coords ----
    const float4* __restrict__ xb = g_xpad + b * N_PTS;
    #pragma unroll
    for (int i = tid; i < N_PTS; i += 512) sxb[i] = xb[i];
    __syncthreads();

    const float4 qc = sxb[n];

    // ---- Phase 1: scan (identical classification arithmetic) ----
    int found = 0;
    for (int pb = 0; pb < N_PTS && found < NSAMPLE; pb += 32) {
        const float4 r = sxb[pb + lane];
        const float dot  = fmaf(qc.z, r.z, fmaf(qc.y, r.y, qc.x * r.x));
        const float dist = (qc.w + r.w) - 2.0f * dot;
        const bool  qual = !(dist > R2);
        const unsigned m = __ballot_sync(0xffffffffu, qual);
        const int need = NSAMPLE - found;
        const int rank = __popc(m & ((1u << lane) - 1u));
        const bool take = qual && (rank < need);
        if (take) sidx[q][found + rank] = pb + lane;
        found += __popc(__ballot_sync(0xffffffffu, take));
    }
    __syncwarp();
    const int lastv = sidx[q][found - 1];    // found >= 1 (self qualifies)
    for (int i = found + lane; i < NSAMPLE; i += 32) sidx[q][i] = lastv;
    __syncwarp();

    // ---- Phase 2: gather-max, 2 rows per LDG.128, 4 chains ----
    const char* __restrict__ fbB =
        reinterpret_cast<const char*>(g_fh + (size_t)b * N_PTS * C_OUT);
    const int half = lane >> 4;              // which of 2 rows per load
    const int lo16 = (lane & 15) * 16;       // byte offset within 256B row

    const __half2 z2 = __float2half2_rn(0.0f);   // relu outputs >= 0
    __half2 a0[4], a1[4], a2[4], a3[4];
    #pragma unroll
    for (int r = 0; r < 4; r++) { a0[r] = z2; a1[r] = z2; a2[r] = z2; a3[r] = z2; }

    #pragma unroll
    for (int j = 0; j < NSAMPLE / 8; j++) {
        const int s = j * 8 + half;
        const int r0 = sidx[q][s + 0];
        const int r1 = sidx[q][s + 2];
        const int r2 = sidx[q][s + 4];
        const int r3 = sidx[q][s + 6];
        const uint4 v0 = *reinterpret_cast<const uint4*>(fbB + r0 * 256 + lo16);
        const uint4 v1 = *reinterpret_cast<const uint4*>(fbB + r1 * 256 + lo16);
        const uint4 v2 = *reinterpret_cast<const uint4*>(fbB + r2 * 256 + lo16);
        const uint4 v3 = *reinterpret_cast<const uint4*>(fbB + r3 * 256 + lo16);
        #pragma unroll
        for (int r = 0; r < 4; r++) {
            a0[r] = __hmax2(a0[r], *reinterpret_cast<const __half2*>(&(&v0.x)[r]));
            a1[r] = __hmax2(a1[r], *reinterpret_cast<const __half2*>(&(&v1.x)[r]));
            a2[r] = __hmax2(a2[r], *reinterpret_cast<const __half2*>(&(&v2.x)[r]));
            a3[r] = __hmax2(a3[r], *reinterpret_cast<const __half2*>(&(&v3.x)[r]));
        }
    }

    __half2 m2[4];
    #pragma unroll
    for (int r = 0; r < 4; r++)
        m2[r] = __hmax2(__hmax2(a0[r], a1[r]), __hmax2(a2[r], a3[r]));

    // combine the two half-warps (each saw half the neighbor slots)
    #pragma unroll
    for (int r = 0; r < 4; r++) {
        const unsigned u = *reinterpret_cast<const unsigned*>(&m2[r]);
        const unsigned o = __shfl_xor_sync(0xffffffffu, u, 16);
        m2[r] = __hmax2(m2[r], *reinterpret_cast<const __half2*>(&o));
    }

    // ---- Phase 3: transpose + coalesced store ----
    // lane covers channels (lane&15)*8 + half*4 .. +3
    const int cbase = (lane & 15) * 8 + half * 4;
    const float2 fA = __half22float2(m2[half * 2 + 0]);
    const float2 fB = __half22float2(m2[half * 2 + 1]);
    sout[cbase + 0][q] = fA.x;
    sout[cbase + 1][q] = fA.y;
    sout[cbase + 2][q] = fB.x;
    sout[cbase + 3][q] = fB.y;
    __syncthreads();

    // out shape (B, 128, N); consecutive tid -> consecutive n (64B runs)
    const int nq = tid & 15;
    const int c0 = tid >> 4;                 // 0..31
    float* ob = out + ((size_t)b * C_OUT) * N_PTS + n0 + nq;
    #pragma unroll
    for (int i = 0; i < 4; i++) {
        const int c = c0 + 32 * i;
        ob[(size_t)c * N_PTS] = sout[c][nq];
    }
}

extern "C" void kernel_launch(void* const* d_in, const int* in_sizes, int n_in,
                              void* d_out, int out_size)
{
    const float* x  = (const float*)d_in[0];
    const float* W1 = (const float*)d_in[1];
    const float* b1 = (const float*)d_in[2];
    const float* W2 = (const float*)d_in[3];
    const float* b2 = (const float*)d_in[4];
    float* out = (float*)d_out;

    feat_kernel<<<NPTS_TOTAL / 32, 128>>>(x, W1, b1, W2, b2);   // 512 blocks
    group_max_kernel<<<NPTS_TOTAL / 16, 512>>>(out);            // 1024 blocks
}